// round 15
// baseline (speedup 1.0000x reference)
#include <cuda_runtime.h>
#include <cstdint>

// ---------------------------------------------------------------------------
// SCAConv via 3xTF32 mma.sync GEMMs.
// Per lm (=l&31): D[row=(h,lhp,b)x1024, col 0..71] =
//   A[row, i=144] x B[i, col]   where A = xu gather, B = [W2 j | b2 | kern o].
// K1 computes D into scratch; K2 adds bias + H·G epilogue.
// ---------------------------------------------------------------------------

typedef unsigned long long ull;

__device__ uint4 g_Bf[32*18*9*32];   // frag-ordered B: [lm][ks][nt][lane]={hi k0, hi k1, lo k0, lo k1}
__device__ float g_D[32*1024*72];    // [lm][h*16+lhp*8+b][col]

__device__ __forceinline__ uint32_t f2tf32(float f) {
    uint32_t u; asm("cvt.rna.tf32.f32 %0, %1;" : "=r"(u) : "f"(f)); return u;
}
__device__ __forceinline__ uint32_t smem_u32(const void* p) {
    return (uint32_t)__cvta_generic_to_shared(p);
}
__device__ __forceinline__ void cp_async16(uint32_t s, const void* g) {
    asm volatile("cp.async.cg.shared.global [%0], [%1], 16;\n" :: "r"(s), "l"(g));
}

#define MMA(d, a0,a1,a2,a3, b0,b1) \
    asm volatile("mma.sync.aligned.m16n8k8.row.col.f32.tf32.tf32.f32 " \
        "{%0,%1,%2,%3},{%4,%5,%6,%7},{%8,%9},{%0,%1,%2,%3};" \
        : "+f"(d[0]),"+f"(d[1]),"+f"(d[2]),"+f"(d[3]) \
        : "r"(a0),"r"(a1),"r"(a2),"r"(a3),"r"(b0),"r"(b1))

// ---------------- prep: frag-ordered hi/lo B ----------------
__global__ void prep_bf(const float* __restrict__ kern, const float* __restrict__ W2,
                        const float* __restrict__ b2) {
    int idx = blockIdx.x*256 + threadIdx.x;
    if (idx >= 32*18*9*32) return;
    int lane = idx & 31;
    int r = idx >> 5;
    int nt = r % 9;  r /= 9;
    int ks = r % 18;
    int lm = r / 18;
    int kq = lane & 3, n = lane >> 2;
    int k0 = ks*8 + kq, k1 = k0 + 4;
    float w0, w1;
    if (nt < 4)      { w0 = W2[(lm*144+k0)*32 + nt*8 + n]; w1 = W2[(lm*144+k1)*32 + nt*8 + n]; }
    else if (nt == 4){ w0 = (n==0) ? b2[lm*144+k0] : 0.f;  w1 = (n==0) ? b2[lm*144+k1] : 0.f; }
    else             { int o = (nt-5)*8 + n; w0 = kern[o*144+k0]; w1 = kern[o*144+k1]; }
    uint32_t h0 = f2tf32(w0), h1 = f2tf32(w1);
    uint32_t l0 = f2tf32(w0 - __uint_as_float(h0));
    uint32_t l1 = f2tf32(w1 - __uint_as_float(h1));
    g_Bf[idx] = make_uint4(h0, h1, l0, l1);
}

// ---------------- K1: GEMM mainloop ----------------
#define PAT_N 13824                 // float2 entries (hi,lo)
#define BS_N  (18*9*32)             // 5184 uint4
#define K1_SMEM (PAT_N*8 + BS_N*16) // 193536 B

__global__ __launch_bounds__(512, 1)
void k1_kernel(const float* __restrict__ x) {
    extern __shared__ char smp[];
    float2* pat = (float2*)smp;
    uint4*  Bs  = (uint4*)(smp + PAT_N*8);

    const int tid = threadIdx.x;
    const int lm  = blockIdx.x >> 2;
    const int hq  = blockIdx.x & 3;

    // stage B frags (once per block)
    for (int i = tid; i < BS_N; i += 512)
        cp_async16(smem_u32(Bs + i), g_Bf + lm*BS_N + i);
    asm volatile("cp.async.commit_group;\n" ::: "memory");

    // stage x patch with tf32 hi/lo split
    // i -> kc(3), lhp(2), b(8), gr(18), c(16); pat[((c*18+gr)*6+lhp*3+kc)*8+b]
    for (int i = tid; i < PAT_N; i += 512) {
        int kc  = i % 3;  int t2 = i / 3;
        int lhp = t2 & 1; t2 >>= 1;
        int b   = t2 & 7; t2 >>= 3;
        int gr  = t2 % 18;
        int c   = t2 / 18;
        int row = hq*16 - 1 + gr;
        int col = lhp*32 + lm - 1 + kc;
        float v = 0.f;
        if (row >= 0 && row < 64 && col >= 0 && col < 64)
            v = x[((b*16 + c)*64 + row)*64 + col];
        uint32_t hv = f2tf32(v);
        uint32_t lv = f2tf32(v - __uint_as_float(hv));
        pat[((c*18 + gr)*6 + lhp*3 + kc)*8 + b] =
            make_float2(__uint_as_float(hv), __uint_as_float(lv));
    }
    asm volatile("cp.async.wait_group 0;\n" ::: "memory");
    __syncthreads();

    const int w    = tid >> 5;          // warp = h-local 0..15
    const int lane = tid & 31;
    const int kq   = lane & 3;
    const int bq   = lane >> 2;
    const int h    = hq*16 + w;

    float d[9][4];
    #pragma unroll
    for (int nt = 0; nt < 9; nt++)
        #pragma unroll
        for (int q = 0; q < 4; q++) d[nt][q] = 0.f;

    #pragma unroll 2
    for (int ks = 0; ks < 18; ks++) {
        int k0 = ks*8 + kq, k1 = k0 + 4;
        int c0 = k0/9, q0 = k0 - 9*c0, kr0 = q0/3, kc0 = q0 - 3*kr0;
        int c1 = k1/9, q1 = k1 - 9*c1, kr1 = q1/3, kc1 = q1 - 3*kr1;
        int o0 = ((c0*18 + w + kr0)*6 + kc0)*8 + bq;   // lhp=0; lhp=1 at +24
        int o1 = ((c1*18 + w + kr1)*6 + kc1)*8 + bq;
        float2 A0 = pat[o0],  A1 = pat[o0 + 24];
        float2 A2 = pat[o1],  A3 = pat[o1 + 24];
        uint32_t a0h = __float_as_uint(A0.x), a1h = __float_as_uint(A1.x);
        uint32_t a2h = __float_as_uint(A2.x), a3h = __float_as_uint(A3.x);
        uint32_t a0l = __float_as_uint(A0.y), a1l = __float_as_uint(A1.y);
        uint32_t a2l = __float_as_uint(A2.y), a3l = __float_as_uint(A3.y);

        const uint4* bp = Bs + ks*(9*32) + lane;
        #pragma unroll
        for (int nt = 0; nt < 9; nt++) {
            uint4 B = bp[nt*32];
            MMA(d[nt], a0h,a1h,a2h,a3h, B.x, B.y);   // hi*hi
            MMA(d[nt], a0h,a1h,a2h,a3h, B.z, B.w);   // hi*lo
            MMA(d[nt], a0l,a1l,a2l,a3l, B.x, B.y);   // lo*hi
        }
    }

    // store D frags: d0/d1 -> row bq (lhp0), d2/d3 -> row bq+8 (lhp1)
    {
        float* base = g_D + (ull)(lm*1024 + h*16 + bq)*72;
        #pragma unroll
        for (int nt = 0; nt < 9; nt++) {
            int col = nt*8 + 2*kq;
            *(float2*)(base + col)        = make_float2(d[nt][0], d[nt][1]);
            *(float2*)(base + 8*72 + col) = make_float2(d[nt][2], d[nt][3]);
        }
    }
}

// ---------------- K2: epilogue ----------------
#define GS_STR 76
#define K2_SMEM ((8*32*GS_STR + 1024 + 32)*4)

__global__ __launch_bounds__(512, 1)
void k2_kernel(const float* __restrict__ bias, const float* __restrict__ cpar,
               const float* __restrict__ W1, const float* __restrict__ b1,
               float* __restrict__ out) {
    extern __shared__ float sm2[];
    float* Gst = sm2;                       // [b][lm][76]
    float* Hs  = sm2 + 8*32*GS_STR;         // [o][j]
    float* bss = Hs + 1024;

    const int tid = threadIdx.x;
    const int lhb = blockIdx.x;
    const int h = lhb >> 1, lhp = lhb & 1;

    for (int i = tid; i < 8*32*72; i += 512) {
        int c = i % 72; int t2 = i / 72;
        int lmi = t2 & 31; int b = t2 >> 5;
        Gst[(b*32 + lmi)*GS_STR + c] =
            g_D[(ull)(lmi*1024 + h*16 + lhp*8 + b)*72 + c];
    }
    for (int i = tid; i < 1024; i += 512) {
        int o = i >> 5, j = i & 31;
        int p = o*128 + lhb;
        float inp[12];
        inp[0] = (float)(p >> 6) * (1.f/64.f);
        inp[1] = 1.f - inp[0];
        inp[2] = (float)(p & 63) * (1.f/64.f);
        inp[3] = 1.f - inp[2];
        #pragma unroll
        for (int k = 0; k < 8; k++) inp[4+k] = cpar[k];
        float s = b1[j];
        #pragma unroll
        for (int k = 0; k < 12; k++) s += W1[j*12 + k] * inp[k];
        Hs[i] = fmaxf(s, 0.f);
    }
    if (tid < 32) bss[tid] = bias[tid];
    __syncthreads();

    const int b   = tid >> 6;
    const int oh  = (tid >> 5) & 1;
    const int lmi = tid & 31;
    const float* gb = Gst + (b*32 + lmi)*GS_STR;

    float g[32];
    #pragma unroll
    for (int q = 0; q < 8; q++) {
        float4 v = *(const float4*)(gb + q*4);
        g[q*4+0] = v.x; g[q*4+1] = v.y; g[q*4+2] = v.z; g[q*4+3] = v.w;
    }
    float tv = gb[32];

    float* ob = out + ((b*32 + oh*16)*64 + h)*64 + lhp*32 + lmi;
    #pragma unroll
    for (int oo = 0; oo < 16; oo++) {
        int o = oh*16 + oo;
        float s = bss[o] + tv + gb[40 + o];
        const float4* h4 = (const float4*)(Hs + o*32);
        #pragma unroll
        for (int q = 0; q < 8; q++) {
            float4 hv = h4[q];
            s += hv.x*g[q*4] + hv.y*g[q*4+1] + hv.z*g[q*4+2] + hv.w*g[q*4+3];
        }
        ob[oo*4096] = s;
    }
}

extern "C" void kernel_launch(void* const* d_in, const int* in_sizes, int n_in,
                              void* d_out, int out_size)
{
    const float* x    = (const float*)d_in[0];   // (8,16,64,64)
    const float* kern = (const float*)d_in[1];   // (32,144)
    const float* bias = (const float*)d_in[2];   // (32,)
    const float* cpar = (const float*)d_in[3];   // (1,8)
    const float* W1   = (const float*)d_in[4];   // (32,12)
    const float* b1   = (const float*)d_in[5];   // (32,)
    const float* W2   = (const float*)d_in[6];   // (4608,32)
    const float* b2   = (const float*)d_in[7];   // (4608,)
    float* out = (float*)d_out;                  // (8,32,64,64)

    cudaFuncSetAttribute(k1_kernel, cudaFuncAttributeMaxDynamicSharedMemorySize, K1_SMEM);
    cudaFuncSetAttribute(k2_kernel, cudaFuncAttributeMaxDynamicSharedMemorySize, K2_SMEM);

    prep_bf<<<648, 256>>>(kern, W2, b2);
    k1_kernel<<<128, 512, K1_SMEM>>>(x);
    k2_kernel<<<128, 512, K2_SMEM>>>(bias, cpar, W1, b1, out);
}